// round 8
// baseline (speedup 1.0000x reference)
#include <cuda_runtime.h>
#include <cuda_bf16.h>

// SSM kernel: out[l, i] = exp(l * a_i) * (B_i * C_i) + D,  a_i = A[i][i]
// L = 262144, n = 256. Output 256 MiB fp32 -> pure streaming-store bound.
//
// Converged at HBM write roofline ~6.3 TB/s. R8 refinement: the R5 grid-
// stride chunk scheme had ~3.7% per-SM imbalance (blocks 0-99 carried an
// extra 64-row chunk). Replace with an EXACT contiguous partition:
// block b owns 590 + (b < 184) consecutive rows -> per-SM imbalance 0.17%.
// Within a block, 4 row-groups interleave at stride 4 (ratio r^4 per step);
// warps share ty so there is no intra-warp divergence. No hop factors,
// no grid-stride loop.

#define N_COLS 256
#define CGROUPS 64              // 64 float4 per row
#define TY 4                    // row interleave stride (256 threads / 64 cols)
#define GRID_BLOCKS 444         // 148 SMs * 3 CTAs (plateau peak: 48 w/SM)

__global__ __launch_bounds__(256, 3)
void ssm_kernel(const float* __restrict__ A,
                const float* __restrict__ B,
                const float* __restrict__ C,
                const float* __restrict__ D,
                float4* __restrict__ out,
                int rows_per, int rem)
{
    const int tx = threadIdx.x & 63;        // column group: cols 4*tx .. 4*tx+3
    const int ty = threadIdx.x >> 6;        // row phase within block (0..3)

    const int b = blockIdx.x;
    const int start = b * rows_per + min(b, rem);        // first row of block
    const int span  = rows_per + (b < rem ? 1 : 0);      // rows in block
    const int end   = start + span;

    const float d = D[0];
    const float LOG2E = 1.4426950408889634f;

    float r4[4], pm[4], bc[4];
#pragma unroll
    for (int k = 0; k < 4; k++) {
        const int j = tx * 4 + k;
        const float a = A[j * N_COLS + j];              // diag (strictly negative)
        const float ra = __expf(a);
        const float ra2 = ra * ra;
        r4[k] = ra2 * ra2;                              // exp(4a): stride-4 ratio
        pm[k] = exp2f((float)(start + ty) * a * LOG2E); // exact anchor at 1st row
        bc[k] = B[j] * C[j];
    }

    // 32-bit addressing: max index L*64 = 2^24 float4 units.
    int base = (start + ty) * CGROUPS + tx;

    for (int row = start + ty; row < end; row += TY) {
        float4 v;
        v.x = fmaf(pm[0], bc[0], d);
        v.y = fmaf(pm[1], bc[1], d);
        v.z = fmaf(pm[2], bc[2], d);
        v.w = fmaf(pm[3], bc[3], d);
        __stcs(&out[base], v);                          // streaming store
        base += TY * CGROUPS;
        pm[0] *= r4[0];
        pm[1] *= r4[1];
        pm[2] *= r4[2];
        pm[3] *= r4[3];
    }
}

extern "C" void kernel_launch(void* const* d_in, const int* in_sizes, int n_in,
                              void* d_out, int out_size)
{
    // Inputs per reference order: (optional scalar L), A (n*n), B (n), C (n), D (1)
    int base = 0;
    if (n_in >= 5) base = n_in - 4;
    const float* A = (const float*)d_in[base + 0];
    const float* B = (const float*)d_in[base + 1];
    const float* C = (const float*)d_in[base + 2];
    const float* D = (const float*)d_in[base + 3];

    const int L = out_size / N_COLS;            // 262144
    const int rows_per = L / GRID_BLOCKS;       // 590
    const int rem      = L % GRID_BLOCKS;       // 184

    ssm_kernel<<<GRID_BLOCKS, 256>>>(A, B, C, D, (float4*)d_out, rows_per, rem);
}

// round 9
// speedup vs baseline: 1.3288x; 1.3288x over previous
#include <cuda_runtime.h>
#include <cuda_bf16.h>

// SSM kernel: out[l, i] = exp(l * a_i) * (B_i * C_i) + D,  a_i = A[i][i]
// L = 262144, n = 256. Output 256 MiB fp32 -> pure streaming-store bound.
//
// Measured law (chip write throughput vs STG batch per loop body):
//   unroll-16 -> 6.30-6.33 TB/s | unroll-8 -> 6.14 | unroll-1 -> 3.4
// R8 lost the unroll (dynamic trip loop) and cratered. R9 keeps BOTH proven
// ingredients:
//   - exact contiguous partition: block b owns 590+(b<184) rows (0.17%/SM
//     imbalance), rows interleaved stride-4 across the 4 row-phases
//   - statically unrolled 16-store inner body (9 full batches/thread) +
//     short tail loop (<16 iters, ~2% of work)

#define N_COLS 256
#define CGROUPS 64              // 64 float4 per row
#define TY 4                    // row interleave stride (256 threads / 64 cols)
#define GRID_BLOCKS 444         // 148 SMs * 3 CTAs (48 w/SM: plateau peak)

__global__ __launch_bounds__(256, 3)
void ssm_kernel(const float* __restrict__ A,
                const float* __restrict__ B,
                const float* __restrict__ C,
                const float* __restrict__ D,
                float4* __restrict__ out,
                int rows_per, int rem)
{
    const int tx = threadIdx.x & 63;        // column group: cols 4*tx .. 4*tx+3
    const int ty = threadIdx.x >> 6;        // row phase within block (0..3)

    const int b = blockIdx.x;
    const int start = b * rows_per + min(b, rem);        // first row of block
    const int span  = rows_per + (b < rem ? 1 : 0);      // rows in block (590/591)
    // this thread covers rows start+ty, start+ty+4, ... below start+span
    const int n_iter = (span - ty + TY - 1) / TY;        // 147 or 148

    const float d = D[0];
    const float LOG2E = 1.4426950408889634f;

    float r4[4], pm[4], bc[4];
#pragma unroll
    for (int k = 0; k < 4; k++) {
        const int j = tx * 4 + k;
        const float a = A[j * N_COLS + j];              // diag (strictly negative)
        const float ra  = __expf(a);
        const float ra2 = ra * ra;
        r4[k] = ra2 * ra2;                              // exp(4a): stride-4 ratio
        pm[k] = exp2f((float)(start + ty) * a * LOG2E); // exact anchor
        bc[k] = B[j] * C[j];
    }

    // 32-bit addressing: max index L*64 = 2^24 float4 units.
    int base = (start + ty) * CGROUPS + tx;

    const int full = n_iter >> 4;           // 9 unrolled-16 batches
    const int tail = n_iter & 15;           // 3..4 leftover rows

    for (int f = 0; f < full; f++) {
#pragma unroll
        for (int l = 0; l < 16; l++) {
            float4 v;
            v.x = fmaf(pm[0], bc[0], d);
            v.y = fmaf(pm[1], bc[1], d);
            v.z = fmaf(pm[2], bc[2], d);
            v.w = fmaf(pm[3], bc[3], d);
            __stcs(&out[base], v);                      // streaming store
            base += TY * CGROUPS;
            pm[0] *= r4[0];
            pm[1] *= r4[1];
            pm[2] *= r4[2];
            pm[3] *= r4[3];
        }
    }
    for (int t = 0; t < tail; t++) {
        float4 v;
        v.x = fmaf(pm[0], bc[0], d);
        v.y = fmaf(pm[1], bc[1], d);
        v.z = fmaf(pm[2], bc[2], d);
        v.w = fmaf(pm[3], bc[3], d);
        __stcs(&out[base], v);
        base += TY * CGROUPS;
        pm[0] *= r4[0];
        pm[1] *= r4[1];
        pm[2] *= r4[2];
        pm[3] *= r4[3];
    }
}

extern "C" void kernel_launch(void* const* d_in, const int* in_sizes, int n_in,
                              void* d_out, int out_size)
{
    // Inputs per reference order: (optional scalar L), A (n*n), B (n), C (n), D (1)
    int base = 0;
    if (n_in >= 5) base = n_in - 4;
    const float* A = (const float*)d_in[base + 0];
    const float* B = (const float*)d_in[base + 1];
    const float* C = (const float*)d_in[base + 2];
    const float* D = (const float*)d_in[base + 3];

    const int L = out_size / N_COLS;            // 262144
    const int rows_per = L / GRID_BLOCKS;       // 590
    const int rem      = L % GRID_BLOCKS;       // 184

    ssm_kernel<<<GRID_BLOCKS, 256>>>(A, B, C, D, (float4*)d_out, rows_per, rem);
}